// round 12
// baseline (speedup 1.0000x reference)
#include <cuda_runtime.h>
#include <cuda_bf16.h>
#include <cstdint>

#define NB 4
#define NC 128
#define NH 256
#define NW 512
#define ND 64
#define W_TILE 64
#define C_TILE 64
#define THREADS 256

// SMEM: A f32 [64c x 128k] (rows 512B, chunk swizzle c^((row&7)<<1)) = 32KB;
//       B bf16 hi/lo [64w x 128k] (rows 256B, chunk swizzle c^(row&7)) = 16KB each.
#define SM_A   0
#define SM_BHI 32768
#define SM_BLO 49152
#define SMEM_TOTAL 65536                // 3 CTAs/SM

__device__ __forceinline__ uint32_t smem_u32(const void* p) {
    uint32_t a;
    asm("{ .reg .u64 t; cvta.to.shared.u64 t, %1; cvt.u32.u64 %0, t; }" : "=r"(a) : "l"(p));
    return a;
}
__device__ __forceinline__ uint32_t f32_off(int row, int k) {
    return (uint32_t)(row * 512 + ((((k >> 2) ^ ((row & 7) << 1)) & 31) << 4) + (k & 3) * 4);
}
__device__ __forceinline__ uint32_t b16_off(int row, int k) {
    return (uint32_t)(row * 256 + (((k >> 3) ^ (row & 7)) << 4) + (k & 7) * 2);
}
__device__ __forceinline__ void bsplit(float x, uint16_t& hi, uint16_t& lo) {
    __nv_bfloat16 h = __float2bfloat16(x);
    __nv_bfloat16 l = __float2bfloat16(x - __bfloat162float(h));
    hi = *reinterpret_cast<uint16_t*>(&h);
    lo = *reinterpret_cast<uint16_t*>(&l);
}
__device__ __forceinline__ uint32_t pack_hi(float2 v) {
    uint32_t r;
    asm("cvt.rn.bf16x2.f32 %0, %1, %2;" : "=r"(r) : "f"(v.y), "f"(v.x));
    return r;
}
__device__ __forceinline__ uint32_t pack_lo(float2 v, uint32_t h) {
    float hx = __uint_as_float(h << 16);
    float hy = __uint_as_float(h & 0xFFFF0000u);
    float2 l = make_float2(v.x - hx, v.y - hy);
    uint32_t r;
    asm("cvt.rn.bf16x2.f32 %0, %1, %2;" : "=r"(r) : "f"(l.y), "f"(l.x));
    return r;
}
__device__ __forceinline__ float2 lds64(uint32_t addr) {
    float2 v;
    asm volatile("ld.shared.v2.f32 {%0,%1}, [%2];" : "=f"(v.x), "=f"(v.y) : "r"(addr));
    return v;
}
__device__ __forceinline__ void ldsm4(uint32_t* r, uint32_t addr) {
    asm volatile("ldmatrix.sync.aligned.m8n8.x4.shared.b16 {%0,%1,%2,%3}, [%4];"
                 : "=r"(r[0]), "=r"(r[1]), "=r"(r[2]), "=r"(r[3]) : "r"(addr));
}
__device__ __forceinline__ void cpasync16(uint32_t dst, const void* src, int sz) {
    asm volatile("cp.async.cg.shared.global [%0], [%1], 16, %2;"
                 :: "r"(dst), "l"(src), "r"(sz) : "memory");
}
__device__ __forceinline__ void mma16816(float* c, const uint32_t* a, const uint32_t* b) {
    asm volatile("mma.sync.aligned.m16n8k16.row.col.f32.bf16.bf16.f32 "
                 "{%0,%1,%2,%3}, {%4,%5,%6,%7}, {%8,%9}, {%0,%1,%2,%3};"
                 : "+f"(c[0]), "+f"(c[1]), "+f"(c[2]), "+f"(c[3])
                 : "r"(a[0]), "r"(a[1]), "r"(a[2]), "r"(a[3]), "r"(b[0]), "r"(b[1]));
}

// Band-pruned mainloop: warp = 16m x 32n. A f32 in-reg split; B bf16 via ldmatrix.
template <int NWARP>
__device__ __forceinline__ void mainloop(uint32_t smb, int m_warp, int qd, int tq,
                                         int b_n, int b_ks, float acc[4][4])
{
    #pragma unroll
    for (int ks = 0; ks < 8; ks++) {
        const bool needA = (ks >= NWARP / 16) && (ks <= NWARP / 16 + 5);
        if (!needA) continue;

        uint32_t ahi[4], alo[4];
        {
            const int k0 = ks * 16 + tq * 2;
            const float2 v00 = lds64(smb + SM_A + f32_off(m_warp + qd,     k0));
            const float2 v10 = lds64(smb + SM_A + f32_off(m_warp + qd + 8, k0));
            const float2 v01 = lds64(smb + SM_A + f32_off(m_warp + qd,     k0 + 8));
            const float2 v11 = lds64(smb + SM_A + f32_off(m_warp + qd + 8, k0 + 8));
            ahi[0] = pack_hi(v00); alo[0] = pack_lo(v00, ahi[0]);
            ahi[1] = pack_hi(v10); alo[1] = pack_lo(v10, ahi[1]);
            ahi[2] = pack_hi(v01); alo[2] = pack_lo(v01, ahi[2]);
            ahi[3] = pack_hi(v11); alo[3] = pack_lo(v11, ahi[3]);
        }

        uint32_t bhi[2][4], blo[2][4];
        #pragma unroll
        for (int p = 0; p < 2; p++) {
            const bool needB = (ks >= NWARP / 16 + p) && (ks <= NWARP / 16 + p + 4);
            if (!needB) continue;
            const int n = NWARP + p * 16 + b_n;
            const uint32_t off = (uint32_t)(n * 256 + (((ks * 2 + b_ks) ^ (n & 7)) << 4));
            ldsm4(bhi[p], smb + SM_BHI + off);
            ldsm4(blo[p], smb + SM_BLO + off);
        }

        #pragma unroll
        for (int nt = 0; nt < 4; nt++) {
            const int nb = NWARP + nt * 8;
            const bool use = (16 * ks <= nb + 70) && (16 * ks + 15 >= nb);
            if (!use) continue;
            const uint32_t* bh = &bhi[nt >> 1][(nt & 1) * 2];
            const uint32_t* bl = &blo[nt >> 1][(nt & 1) * 2];
            mma16816(acc[nt], ahi, bh);
            mma16816(acc[nt], ahi, bl);
            mma16816(acc[nt], alo, bh);
        }
    }
}

__global__ void __launch_bounds__(THREADS, 3)
corr_mma_kernel(const float* __restrict__ h1,
                const float* __restrict__ cost,
                float* __restrict__ out)
{
    extern __shared__ char smem[];
    const uint32_t smb = smem_u32(smem);
    const int tid  = threadIdx.x;
    const int wid  = tid >> 5;
    const int lane = tid & 31;

    // cs fastest in grid.x so the two c-slices of one (wt,hh,bb) run adjacently
    // -> second CTA's cost read hits L2.
    const int cs = blockIdx.x & 1;        // channel slice 0..1
    const int wt = blockIdx.x >> 1;       // w-tile 0..7
    const int hh = blockIdx.y;
    const int bb = blockIdx.z;
    const int w0 = wt * W_TILE;
    const int c0 = cs * C_TILE;

    // ---- cost LDG first (16 floats/thread) ----
    float4 cv[4];
    int cd[4], cw[4];
    #pragma unroll
    for (int j = 0; j < 4; j++) {
        const int idx = j * THREADS + tid;
        cd[j] = idx >> 4;
        cw[j] = (idx & 15) * 4;
        cv[j] = *reinterpret_cast<const float4*>(
                    cost + (((size_t)bb * ND + cd[j]) * NH + hh) * NW + w0 + cw[j]);
    }

    // ---- A tile via cp.async: 2048 chunks, 8/thread ----
    {
        #pragma unroll
        for (int j = 0; j < 8; j++) {
            const int idx = j * THREADS + tid;
            const int row = idx >> 5;          // 0..63
            const int c4  = idx & 31;
            const int gw  = w0 + c4 * 4;
            const uint32_t dst = smb + SM_A + (uint32_t)(row * 512 + ((c4 ^ ((row & 7) << 1)) << 4));
            const float* src = h1 + (((size_t)bb * NC + c0 + row) * NH + hh) * NW + gw;
            cpasync16(dst, src, gw < NW ? 16 : 0);
        }
        asm volatile("cp.async.commit_group;" ::: "memory");
    }

    // ---- sparse-zero B stripes: 512 chunk-zeros, 2/thread ----
    {
        const uint4 z = make_uint4(0, 0, 0, 0);
        #pragma unroll
        for (int i = 0; i < 2; i++) {
            const int idx  = tid * 2 + i;
            const int tile = idx >> 8;
            const int rr   = idx & 255;
            const int row  = rr >> 2;
            const int cc   = rr & 3;
            const int chunk = 2 * (row >> 4) + (cc & 1) + (cc >> 1) * 8;
            const uint32_t off = b16_off(row, chunk * 8);
            *reinterpret_cast<uint4*>(smem + (tile ? SM_BLO : SM_BHI) + off) = z;
        }
    }

    // zero-stripes and scatter overlap within chunks -> must order (R9 lesson)
    __syncthreads();

    // ---- shear-scatter cost -> B hi/lo: B[w][w+d] = cost[d][w] ----
    {
        #pragma unroll
        for (int j = 0; j < 4; j++) {
            const float x[4] = {cv[j].x, cv[j].y, cv[j].z, cv[j].w};
            #pragma unroll
            for (int e = 0; e < 4; e++) {
                const int w = cw[j] + e;
                const uint32_t off = b16_off(w, w + cd[j]);
                uint16_t hi, lo;
                bsplit(x[e], hi, lo);
                *reinterpret_cast<uint16_t*>(smem + SM_BHI + off) = hi;
                *reinterpret_cast<uint16_t*>(smem + SM_BLO + off) = lo;
            }
        }
    }

    asm volatile("cp.async.wait_group 0;" ::: "memory");
    __syncthreads();

    // ---- warp-tile GEMM: 8 warps of 16m x 32n cover 64x64 ----
    const int m_warp = (wid & 3) * 16;
    const int n_warp = (wid >> 2) * 32;
    const int qd = lane >> 2;
    const int tq = lane & 3;

    const int sub  = lane >> 3;
    const int rid  = lane & 7;
    const int b_n  = (sub >> 1) * 8 + rid;
    const int b_ks = (sub & 1);

    float acc[4][4];
    #pragma unroll
    for (int nt = 0; nt < 4; nt++)
        #pragma unroll
        for (int e = 0; e < 4; e++) acc[nt][e] = 0.f;

    if (n_warp == 0)
        mainloop<0>(smb, m_warp, qd, tq, b_n, b_ks, acc);
    else
        mainloop<32>(smb, m_warp, qd, tq, b_n, b_ks, acc);

    // ---- Epilogue ----
    {
        const int m0 = c0 + m_warp + qd;
        float* r0 = out + (((size_t)bb * NC + m0) * NH + hh) * NW + w0 + n_warp;
        float* r1 = out + (((size_t)bb * NC + m0 + 8) * NH + hh) * NW + w0 + n_warp;
        #pragma unroll
        for (int nt = 0; nt < 4; nt++) {
            const int nc2 = nt * 8 + tq * 2;
            *reinterpret_cast<float2*>(r0 + nc2) = make_float2(acc[nt][0], acc[nt][1]);
            *reinterpret_cast<float2*>(r1 + nc2) = make_float2(acc[nt][2], acc[nt][3]);
        }
    }
}

extern "C" void kernel_launch(void* const* d_in, const int* in_sizes, int n_in,
                              void* d_out, int out_size)
{
    const float* h1   = (const float*)d_in[0];
    const float* cost = (const float*)d_in[1];
    float* out        = (float*)d_out;

    cudaFuncSetAttribute(corr_mma_kernel, cudaFuncAttributeMaxDynamicSharedMemorySize, SMEM_TOTAL);

    dim3 grid((NW / W_TILE) * (NC / C_TILE), NH, NB);
    corr_mma_kernel<<<grid, THREADS, SMEM_TOTAL>>>(h1, cost, out);
}